// round 13
// baseline (speedup 1.0000x reference)
#include <cuda_runtime.h>
#include <math.h>
#include <stdint.h>

// Problem constants
#define BB_    8
#define LL_    512
#define HEADS_ 12
#define HS_    64
#define HID_   768
#define OD_    1536          // HEADS*2*HS
#define M1_    (BB_*LL_)     // 4096
#define BH_    (BB_*HEADS_)  // 96
#define NEG_INF_F (-3.4028234663852886e38f)

// Scratch (device globals — no allocations allowed)
__device__ uint8_t g_Af8[M1_ * HID_];     // inputs e4m3 [4096][768]
__device__ uint8_t g_WTf8[OD_ * HID_];    // W^T e4m3 [1536][768]
__device__ uint8_t g_q8[BH_ * LL_ * HS_]; // [b*h][l][d] e4m3
__device__ uint8_t g_k8[BH_ * LL_ * HS_];
__device__ float g_sin[LL_ * 32];
__device__ float g_cos[LL_ * 32];

// Below-diagonal (tm,tn) tile enumeration: 28 tiles per bh
__device__ const int c_tm[28] = {1,2,2,3,3,3,4,4,4,4,5,5,5,5,5,
                                 6,6,6,6,6,6,7,7,7,7,7,7,7};
__device__ const int c_tn[28] = {0,0,1,0,1,2,0,1,2,3,0,1,2,3,4,
                                 0,1,2,3,4,5,0,1,2,3,4,5,6};

// ---------------------------------------------------------------------------
// PTX helpers (portable ISA only — compute_103 target has no 'a' features)
// ---------------------------------------------------------------------------
__device__ __forceinline__ uint32_t smem_u32(const void* p) {
    return (uint32_t)__cvta_generic_to_shared(p);
}
__device__ __forceinline__ void cp16(uint32_t s, const void* g) {
    asm volatile("cp.async.cg.shared.global [%0], [%1], 16;\n" :: "r"(s), "l"(g));
}
#define CP_COMMIT() asm volatile("cp.async.commit_group;\n")
#define CP_WAIT0()  asm volatile("cp.async.wait_group 0;\n")
#define CP_WAIT2()  asm volatile("cp.async.wait_group 2;\n")

// cvt packs first source into the HIGH byte: d = {hi, lo}
__device__ __forceinline__ uint16_t f2e4m3x2(float hi, float lo) {
    uint16_t r;
    asm("cvt.rn.satfinite.e4m3x2.f32 %0, %1, %2;\n" : "=h"(r) : "f"(hi), "f"(lo));
    return r;
}

__device__ __forceinline__ void ldsm_x4(uint32_t* r, const void* p) {
    uint32_t a = smem_u32(p);
    asm volatile("ldmatrix.sync.aligned.m8n8.x4.shared.b16 {%0,%1,%2,%3},[%4];"
                 : "=r"(r[0]), "=r"(r[1]), "=r"(r[2]), "=r"(r[3]) : "r"(a));
}

// D += A(m16k32) * B(k32n8), e4m3 in, f32 accum
__device__ __forceinline__ void mma_fp8(float* d, const uint32_t* a, const uint32_t* b) {
    asm volatile(
        "mma.sync.aligned.m16n8k32.row.col.f32.e4m3.e4m3.f32 "
        "{%0,%1,%2,%3},{%4,%5,%6,%7},{%8,%9},{%0,%1,%2,%3};\n"
        : "+f"(d[0]), "+f"(d[1]), "+f"(d[2]), "+f"(d[3])
        : "r"(a[0]), "r"(a[1]), "r"(a[2]), "r"(a[3]), "r"(b[0]), "r"(b[1]));
}

// Streaming (evict-first) stores for write-once output
__device__ __forceinline__ void stg_cs_f2(float* p, float x, float y) {
    asm volatile("st.global.cs.v2.f32 [%0], {%1,%2};\n" :: "l"(p), "f"(x), "f"(y) : "memory");
}
__device__ __forceinline__ void stg_cs_f4(float* p, float4 v) {
    asm volatile("st.global.cs.v4.f32 [%0], {%1,%2,%3,%4};\n"
                 :: "l"(p), "f"(v.x), "f"(v.y), "f"(v.z), "f"(v.w) : "memory");
}

// ---------------------------------------------------------------------------
// Kernel 0: merged prep — below-diag output fills (idle BW here!),
// A->e4m3 (MLP=4), RoPE tables, W transpose->e4m3
// ---------------------------------------------------------------------------
#define NFILL_ (BH_ * 7)                    // 672 fill blocks (4 tiles each)
#define NA4_   ((M1_ * HID_) / 4)           // 786432 float4s of A
#define NAB_   (NA4_ / 1024)                // 768 A-convert blocks
#define NT_    (LL_ * 32)                   // 16384 table entries
#define NTB_   (NT_ / 256)                  // 64 table blocks
#define NTRB_  ((OD_ / 32) * (HID_ / 32))   // 1152 transpose blocks

__global__ void __launch_bounds__(256)
prep_all(const float* __restrict__ A, const float* __restrict__ W,
         float* __restrict__ out) {
    const int bid = blockIdx.x;
    const int tid = threadIdx.x;
    if (bid < NFILL_) {
        // Fill 4 below-diagonal 64x64 tiles with neg-inf (pure streaming store)
        const int bh = bid / 7;
        const int j  = bid % 7;
        float* ob = out + (size_t)bh * LL_ * LL_;
        const float4 nv = make_float4(NEG_INF_F, NEG_INF_F, NEG_INF_F, NEG_INF_F);
        #pragma unroll
        for (int q = 0; q < 4; q++) {
            const int k  = j * 4 + q;
            float* tb = ob + (size_t)(c_tm[k] * 64) * LL_ + c_tn[k] * 64;
            #pragma unroll
            for (int i = 0; i < 4; i++) {
                int idx = tid + 256 * i;          // 0..1023
                int r = idx >> 4;
                int c = (idx & 15) * 4;
                stg_cs_f4(&tb[(size_t)r * LL_ + c], nv);
            }
        }
        return;
    }
    if (bid < NFILL_ + NAB_) {
        const int base = (bid - NFILL_) * 1024 + tid;
        float4 v0 = ((const float4*)A)[base];
        float4 v1 = ((const float4*)A)[base + 256];
        float4 v2 = ((const float4*)A)[base + 512];
        float4 v3 = ((const float4*)A)[base + 768];
        uint32_t r0 = (uint32_t)f2e4m3x2(v0.y, v0.x) | ((uint32_t)f2e4m3x2(v0.w, v0.z) << 16);
        uint32_t r1 = (uint32_t)f2e4m3x2(v1.y, v1.x) | ((uint32_t)f2e4m3x2(v1.w, v1.z) << 16);
        uint32_t r2 = (uint32_t)f2e4m3x2(v2.y, v2.x) | ((uint32_t)f2e4m3x2(v2.w, v2.z) << 16);
        uint32_t r3 = (uint32_t)f2e4m3x2(v3.y, v3.x) | ((uint32_t)f2e4m3x2(v3.w, v3.z) << 16);
        ((uint32_t*)g_Af8)[base]       = r0;
        ((uint32_t*)g_Af8)[base + 256] = r1;
        ((uint32_t*)g_Af8)[base + 512] = r2;
        ((uint32_t*)g_Af8)[base + 768] = r3;
        return;
    }
    if (bid < NFILL_ + NAB_ + NTB_) {
        int j = (bid - NFILL_ - NAB_) * 256 + tid;
        int l = j >> 5;
        int p = j & 31;
        float inv = powf(10000.0f, -(float)p / 32.0f);
        float ang = (float)l * inv;
        g_sin[j] = sinf(ang);
        g_cos[j] = cosf(ang);
        return;
    }
    __shared__ float tile[32][33];
    const int b2 = bid - NFILL_ - NAB_ - NTB_;
    const int bx = b2 % (OD_ / 32);
    const int by = b2 / (OD_ / 32);
    {
        const int c  = tid & 31;
        const int r4 = tid >> 5;
        #pragma unroll
        for (int i = 0; i < 4; i++) {
            int r = r4 * 4 + i;
            tile[r][c] = W[(size_t)(by * 32 + r) * OD_ + bx * 32 + c];
        }
    }
    __syncthreads();
    {
        const int r  = tid >> 3;
        const int cg = tid & 7;
        uint32_t val = 0;
        #pragma unroll
        for (int j = 0; j < 4; j++) {
            uint32_t b = f2e4m3x2(0.0f, tile[cg * 4 + j][r]) & 0xFF;
            val |= b << (8 * j);
        }
        *(uint32_t*)&g_WTf8[(size_t)(bx * 32 + r) * HID_ + by * 32 + cg * 4] = val;
    }
}

// ---------------------------------------------------------------------------
// Kernel 1: X = A @ W + b (4096x1536, K=768), fp8 mma m16n8k32.
// FROZEN R5/R8 configuration (measured-best). No fills here (R10 lesson).
// ---------------------------------------------------------------------------
#define A8_STRIDE   80
#define TILE8_BYTES (128 * A8_STRIDE)      // 10240
#define STAGE8      (2 * TILE8_BYTES)      // 20480
#define G1_DSMEM    (4 * STAGE8)           // 81920

__global__ void __launch_bounds__(256, 2)
gemm1_fp8(const float* __restrict__ bias) {
    extern __shared__ uint8_t sm8[];

    const int t    = threadIdx.x;
    const int lane = t & 31;
    const int warp = t >> 5;
    const int g    = lane >> 2;
    const int tig  = lane & 3;
    const int wm   = warp >> 1;     // 0..3
    const int wn   = warp & 1;      // 0..1
    const int m0   = blockIdx.y * 128;
    const int n0   = blockIdx.x * 128;

    float acc[2][8][4];
    #pragma unroll
    for (int mt = 0; mt < 2; mt++)
        #pragma unroll
        for (int j = 0; j < 8; j++)
            #pragma unroll
            for (int c = 0; c < 4; c++) acc[mt][j][c] = 0.0f;

    auto load_tile = [&](int buf, int k0) {
        uint8_t* as = sm8 + buf * STAGE8;
        uint8_t* bs = as + TILE8_BYTES;
        #pragma unroll
        for (int i = 0; i < 2; i++) {
            int ch = t + 256 * i;
            int r = ch >> 2;
            int cc = (ch & 3) * 16;
            cp16(smem_u32(as + r * A8_STRIDE + cc),
                 g_Af8 + (size_t)(m0 + r) * HID_ + k0 + cc);
        }
        #pragma unroll
        for (int i = 0; i < 2; i++) {
            int ch = t + 256 * i;
            int r = ch >> 2;
            int cc = (ch & 3) * 16;
            cp16(smem_u32(bs + r * A8_STRIDE + cc),
                 g_WTf8 + (size_t)(n0 + r) * HID_ + k0 + cc);
        }
        CP_COMMIT();
    };

    load_tile(0, 0);
    load_tile(1, 64);
    load_tile(2, 128);

    const int a_row  = lane & 15;
    const int a_coff = (lane >> 4) * 16;
    const int b_row  = (lane & 7) + 8 * (lane >> 4);
    const int b_coff = 16 * ((lane >> 3) & 1);

    for (int kt = 0; kt < 12; kt++) {
        const int buf = kt & 3;
        CP_WAIT2();
        __syncthreads();
        if (kt + 3 < 12) load_tile((kt + 3) & 3, (kt + 3) * 64);
        else             CP_COMMIT();   // keep group count uniform for WAIT2

        const uint8_t* as = sm8 + buf * STAGE8;
        const uint8_t* bs = as + TILE8_BYTES;

        #pragma unroll
        for (int kk = 0; kk < 2; kk++) {
            const int k32 = kk * 32;
            uint32_t af[2][4];
            #pragma unroll
            for (int mt = 0; mt < 2; mt++) {
                int row = wm * 32 + mt * 16 + a_row;
                ldsm_x4(af[mt], as + row * A8_STRIDE + k32 + a_coff);
            }
            #pragma unroll
            for (int nt = 0; nt < 4; nt++) {
                uint32_t bf[4];
                int row = wn * 64 + nt * 16 + b_row;
                ldsm_x4(bf, bs + row * A8_STRIDE + k32 + b_coff);
                mma_fp8(acc[0][2 * nt],     af[0], &bf[0]);
                mma_fp8(acc[0][2 * nt + 1], af[0], &bf[2]);
                mma_fp8(acc[1][2 * nt],     af[1], &bf[0]);
                mma_fp8(acc[1][2 * nt + 1], af[1], &bf[2]);
            }
        }
    }

    // Epilogue: bias + RoPE + e4m3 scatter to g_q8/g_k8 ([b*h][l][d])
    #pragma unroll
    for (int mt = 0; mt < 2; mt++) {
        #pragma unroll
        for (int half = 0; half < 2; half++) {
            const int m  = m0 + wm * 32 + mt * 16 + g + half * 8;
            const int l  = m & (LL_ - 1);
            const int b_ = m >> 9;
            #pragma unroll
            for (int j = 0; j < 8; j++) {
                const int n = n0 + wn * 64 + j * 8 + 2 * tig;   // even col
                float e = acc[mt][j][half * 2 + 0] + bias[n];
                float o = acc[mt][j][half * 2 + 1] + bias[n + 1];
                const int h  = n >> 7;
                const int qk = (n >> 6) & 1;
                const int d  = n & 63;
                const int p  = d >> 1;
                const float s  = g_sin[l * 32 + p];
                const float co = g_cos[l * 32 + p];
                uint16_t v = f2e4m3x2(e * s + o * co, e * co - o * s);
                uint8_t* dst = (qk ? g_k8 : g_q8)
                    + ((size_t)(b_ * HEADS_ + h) * LL_ + l) * HS_ + d;
                *(uint16_t*)dst = v;
            }
        }
    }
}

// ---------------------------------------------------------------------------
// Kernel 2: logits = (q.k)/8, masked; fp8 mma, ROW-PERSISTENT blocks.
// Fills handled by prep — this kernel only computes tn >= tm tiles.
// ---------------------------------------------------------------------------
#define QK8_STRIDE 80

__global__ void __launch_bounds__(128)
attn_logits_fp8(const int* __restrict__ am, float* __restrict__ out) {
    const int tm = blockIdx.x;        // 0..7 (tm=0 = longest row, launches first)
    const int bh = blockIdx.y;        // 0..95
    const int t  = threadIdx.x;
    const int b_ = bh / HEADS_;
    const int m0 = tm * 64;
    float* obase = out + (size_t)bh * LL_ * LL_;

    __shared__ uint8_t Qs[64 * QK8_STRIDE];
    __shared__ uint8_t Ks[2][64 * QK8_STRIDE];
    __shared__ int amrow[LL_];

    const uint8_t* qb = g_q8 + ((size_t)bh * LL_ + m0) * HS_;
    const uint8_t* kb = g_k8 + ((size_t)bh * LL_ + tm * 64) * HS_;   // tn=tm tile

    #pragma unroll
    for (int i = 0; i < 2; i++) {
        int ch = t + 128 * i;
        int r = ch >> 2;
        int c = (ch & 3) * 16;
        cp16(smem_u32(&Qs[r * QK8_STRIDE + c]), qb + r * HS_ + c);
        cp16(smem_u32(&Ks[0][r * QK8_STRIDE + c]), kb + r * HS_ + c);
    }
    CP_COMMIT();
    #pragma unroll
    for (int i = 0; i < 4; i++) amrow[t + 128 * i] = am[b_ * LL_ + t + 128 * i];

    CP_WAIT0();
    __syncthreads();

    const int lane = t & 31;
    const int warp = t >> 5;
    const int g    = lane >> 2;
    const int tig  = lane & 3;
    const int wm   = warp >> 1;
    const int wn   = warp & 1;

    const int a_row  = lane & 15;
    const int a_coff = (lane >> 4) * 16;
    const int b_row  = (lane & 7) + 8 * (lane >> 4);
    const int b_coff = 16 * ((lane >> 3) & 1);

    // Hoist Q fragments once (reused for every tn)
    uint32_t qf[2][4], qf2[2][4];
    #pragma unroll
    for (int mt = 0; mt < 2; mt++) {
        int row = wm * 32 + mt * 16 + a_row;
        ldsm_x4(qf[mt],  &Qs[row * QK8_STRIDE + a_coff]);       // k32=0
        ldsm_x4(qf2[mt], &Qs[row * QK8_STRIDE + 32 + a_coff]);  // k32=32
    }

    int buf = 0;
    for (int tn = tm; tn < 8; tn++) {
        if (tn + 1 < 8) {
            const uint8_t* kn = g_k8 + ((size_t)bh * LL_ + (tn + 1) * 64) * HS_;
            #pragma unroll
            for (int i = 0; i < 2; i++) {
                int ch = t + 128 * i;
                int r = ch >> 2;
                int c = (ch & 3) * 16;
                cp16(smem_u32(&Ks[buf ^ 1][r * QK8_STRIDE + c]), kn + r * HS_ + c);
            }
            CP_COMMIT();
        }

        const int n0 = tn * 64;
        float acc[2][4][4];
        #pragma unroll
        for (int mt = 0; mt < 2; mt++)
            #pragma unroll
            for (int j = 0; j < 4; j++)
                #pragma unroll
                for (int c = 0; c < 4; c++) acc[mt][j][c] = 0.0f;

        #pragma unroll
        for (int nt = 0; nt < 2; nt++) {
            uint32_t kf[4];
            int row = wn * 32 + nt * 16 + b_row;
            ldsm_x4(kf, &Ks[buf][row * QK8_STRIDE + b_coff]);           // k32=0
            mma_fp8(acc[0][2 * nt],     qf[0], &kf[0]);
            mma_fp8(acc[0][2 * nt + 1], qf[0], &kf[2]);
            mma_fp8(acc[1][2 * nt],     qf[1], &kf[0]);
            mma_fp8(acc[1][2 * nt + 1], qf[1], &kf[2]);
            ldsm_x4(kf, &Ks[buf][row * QK8_STRIDE + 32 + b_coff]);      // k32=32
            mma_fp8(acc[0][2 * nt],     qf2[0], &kf[0]);
            mma_fp8(acc[0][2 * nt + 1], qf2[0], &kf[2]);
            mma_fp8(acc[1][2 * nt],     qf2[1], &kf[0]);
            mma_fp8(acc[1][2 * nt + 1], qf2[1], &kf[2]);
        }

        const bool diag = (tn == tm);
        #pragma unroll
        for (int mt = 0; mt < 2; mt++) {
            #pragma unroll
            for (int half = 0; half < 2; half++) {
                const int mi = wm * 32 + mt * 16 + g + half * 8;
                const int m  = m0 + mi;
                const bool rok = (amrow[m] != 0);
                #pragma unroll
                for (int j = 0; j < 4; j++) {
                    const int ni = wn * 32 + j * 8 + 2 * tig;
                    const int n  = n0 + ni;
                    float x0 = acc[mt][j][half * 2 + 0] * 0.125f;
                    float x1 = acc[mt][j][half * 2 + 1] * 0.125f;
                    bool k0 = !rok || amrow[n] == 0;
                    bool k1 = !rok || amrow[n + 1] == 0;
                    if (diag) { k0 |= (m > n); k1 |= (m > n + 1); }
                    if (k0) x0 = NEG_INF_F;
                    if (k1) x1 = NEG_INF_F;
                    stg_cs_f2(&obase[(size_t)m * LL_ + n], x0, x1);
                }
            }
        }

        if (tn + 1 < 8) {
            CP_WAIT0();
            __syncthreads();
        }
        buf ^= 1;
    }
}

// ---------------------------------------------------------------------------
// Entry point
// ---------------------------------------------------------------------------
extern "C" void kernel_launch(void* const* d_in, const int* in_sizes, int n_in,
                              void* d_out, int out_size) {
    const float* inputs = (const float*)d_in[0];  // [8,512,768]
    const float* W      = (const float*)d_in[1];  // [768,1536]
    const float* bias   = (const float*)d_in[2];  // [1536]
    const int*   amask  = (const int*)d_in[3];    // [8,512]
    float* out = (float*)d_out;                   // [8,12,512,512]

    cudaFuncSetAttribute(gemm1_fp8,
                         cudaFuncAttributeMaxDynamicSharedMemorySize, G1_DSMEM);

    prep_all<<<NFILL_ + NAB_ + NTB_ + NTRB_, 256>>>(inputs, W, out);
    gemm1_fp8<<<dim3(OD_ / 128, M1_ / 128), 256, G1_DSMEM>>>(bias);
    attn_logits_fp8<<<dim3(LL_ / 64, BH_), 128>>>(amask, out);
}

// round 15
// speedup vs baseline: 1.0732x; 1.0732x over previous
#include <cuda_runtime.h>
#include <math.h>
#include <stdint.h>

// Problem constants
#define BB_    8
#define LL_    512
#define HEADS_ 12
#define HS_    64
#define HID_   768
#define OD_    1536          // HEADS*2*HS
#define M1_    (BB_*LL_)     // 4096
#define BH_    (BB_*HEADS_)  // 96
#define NEG_INF_F (-3.4028234663852886e38f)

// Scratch (device globals — no allocations allowed)
__device__ uint8_t g_Af8[M1_ * HID_];     // inputs e4m3 [4096][768]
__device__ uint8_t g_WTf8[OD_ * HID_];    // W^T e4m3 [1536][768]
__device__ uint8_t g_q8[BH_ * LL_ * HS_]; // [b*h][l][d] e4m3
__device__ uint8_t g_k8[BH_ * LL_ * HS_];
__device__ float g_sin[LL_ * 32];
__device__ float g_cos[LL_ * 32];
__device__ int   g_flag[BH_];             // per-(b,h) producer counter

// ---------------------------------------------------------------------------
// PTX helpers (portable ISA only — compute_103 target has no 'a' features)
// ---------------------------------------------------------------------------
__device__ __forceinline__ uint32_t smem_u32(const void* p) {
    return (uint32_t)__cvta_generic_to_shared(p);
}
__device__ __forceinline__ void cp16(uint32_t s, const void* g) {
    asm volatile("cp.async.cg.shared.global [%0], [%1], 16;\n" :: "r"(s), "l"(g));
}
#define CP_COMMIT() asm volatile("cp.async.commit_group;\n")
#define CP_WAIT0()  asm volatile("cp.async.wait_group 0;\n")
#define CP_WAIT2()  asm volatile("cp.async.wait_group 2;\n")

__device__ __forceinline__ uint16_t f2e4m3x2(float hi, float lo) {
    uint16_t r;
    asm("cvt.rn.satfinite.e4m3x2.f32 %0, %1, %2;\n" : "=h"(r) : "f"(hi), "f"(lo));
    return r;
}

__device__ __forceinline__ void ldsm_x4(uint32_t* r, const void* p) {
    uint32_t a = smem_u32(p);
    asm volatile("ldmatrix.sync.aligned.m8n8.x4.shared.b16 {%0,%1,%2,%3},[%4];"
                 : "=r"(r[0]), "=r"(r[1]), "=r"(r[2]), "=r"(r[3]) : "r"(a));
}

__device__ __forceinline__ void mma_fp8(float* d, const uint32_t* a, const uint32_t* b) {
    asm volatile(
        "mma.sync.aligned.m16n8k32.row.col.f32.e4m3.e4m3.f32 "
        "{%0,%1,%2,%3},{%4,%5,%6,%7},{%8,%9},{%0,%1,%2,%3};\n"
        : "+f"(d[0]), "+f"(d[1]), "+f"(d[2]), "+f"(d[3])
        : "r"(a[0]), "r"(a[1]), "r"(a[2]), "r"(a[3]), "r"(b[0]), "r"(b[1]));
}

__device__ __forceinline__ void stg_cs_f2(float* p, float x, float y) {
    asm volatile("st.global.cs.v2.f32 [%0], {%1,%2};\n" :: "l"(p), "f"(x), "f"(y) : "memory");
}
__device__ __forceinline__ void stg_cs_f4(float* p, float4 v) {
    asm volatile("st.global.cs.v4.f32 [%0], {%1,%2,%3,%4};\n"
                 :: "l"(p), "f"(v.x), "f"(v.y), "f"(v.z), "f"(v.w) : "memory");
}

__device__ __forceinline__ int ld_acq(const int* p) {
    int v;
    asm volatile("ld.acquire.gpu.global.b32 %0, [%1];" : "=r"(v) : "l"(p) : "memory");
    return v;
}

// ---------------------------------------------------------------------------
// Kernel 0: merged prep — A->e4m3 (MLP=4), RoPE tables, W transpose, flag zero
// ---------------------------------------------------------------------------
#define NA4_   ((M1_ * HID_) / 4)           // 786432 float4s of A
#define NAB_   (NA4_ / 1024)                // 768 A-convert blocks
#define NT_    (LL_ * 32)                   // 16384 table entries
#define NTB_   (NT_ / 256)                  // 64 table blocks
#define NTRB_  ((OD_ / 32) * (HID_ / 32))   // 1152 transpose blocks

__global__ void __launch_bounds__(256)
prep_all(const float* __restrict__ A, const float* __restrict__ W) {
    const int bid = blockIdx.x;
    const int tid = threadIdx.x;
    if (bid < NAB_) {
        const int base = bid * 1024 + tid;
        float4 v0 = ((const float4*)A)[base];
        float4 v1 = ((const float4*)A)[base + 256];
        float4 v2 = ((const float4*)A)[base + 512];
        float4 v3 = ((const float4*)A)[base + 768];
        uint32_t r0 = (uint32_t)f2e4m3x2(v0.y, v0.x) | ((uint32_t)f2e4m3x2(v0.w, v0.z) << 16);
        uint32_t r1 = (uint32_t)f2e4m3x2(v1.y, v1.x) | ((uint32_t)f2e4m3x2(v1.w, v1.z) << 16);
        uint32_t r2 = (uint32_t)f2e4m3x2(v2.y, v2.x) | ((uint32_t)f2e4m3x2(v2.w, v2.z) << 16);
        uint32_t r3 = (uint32_t)f2e4m3x2(v3.y, v3.x) | ((uint32_t)f2e4m3x2(v3.w, v3.z) << 16);
        ((uint32_t*)g_Af8)[base]       = r0;
        ((uint32_t*)g_Af8)[base + 256] = r1;
        ((uint32_t*)g_Af8)[base + 512] = r2;
        ((uint32_t*)g_Af8)[base + 768] = r3;
        return;
    }
    if (bid < NAB_ + NTB_) {
        int j = (bid - NAB_) * 256 + tid;
        int l = j >> 5;
        int p = j & 31;
        float inv = powf(10000.0f, -(float)p / 32.0f);
        float ang = (float)l * inv;
        g_sin[j] = sinf(ang);
        g_cos[j] = cosf(ang);
        return;
    }
    if (bid < NAB_ + NTB_ + NTRB_) {
        __shared__ float tile[32][33];
        const int b2 = bid - NAB_ - NTB_;
        const int bx = b2 % (OD_ / 32);
        const int by = b2 / (OD_ / 32);
        {
            const int c  = tid & 31;
            const int r4 = tid >> 5;
            #pragma unroll
            for (int i = 0; i < 4; i++) {
                int r = r4 * 4 + i;
                tile[r][c] = W[(size_t)(by * 32 + r) * OD_ + bx * 32 + c];
            }
        }
        __syncthreads();
        {
            const int r  = tid >> 3;
            const int cg = tid & 7;
            uint32_t val = 0;
            #pragma unroll
            for (int j = 0; j < 4; j++) {
                uint32_t b = f2e4m3x2(0.0f, tile[cg * 4 + j][r]) & 0xFF;
                val |= b << (8 * j);
            }
            *(uint32_t*)&g_WTf8[(size_t)(bx * 32 + r) * HID_ + by * 32 + cg * 4] = val;
        }
        return;
    }
    // flag zero block
    if (tid < BH_) g_flag[tid] = 0;
}

// ---------------------------------------------------------------------------
// Kernel 1: FUSED gemm1 + attn.
//   bid <  384: gemm CTA (frozen R5/R8 config), then release flag[bh].
//   bid >= 384: attn CTA = 2 x 128-thread groups (tm pair), fills first
//               (overlap gemm), spin on flag[bh]==4, then R9 inner loop.
// ---------------------------------------------------------------------------
#define A8_STRIDE   80
#define TILE8_BYTES (128 * A8_STRIDE)      // 10240
#define STAGE8      (2 * TILE8_BYTES)      // 20480
#define G1_DSMEM    (4 * STAGE8)           // 81920
#define G_CTAS      384
#define QK8_STRIDE  80

__global__ void __launch_bounds__(256, 2)
fused_gemm_attn(const float* __restrict__ bias,
                const int* __restrict__ am,
                float* __restrict__ out) {
    extern __shared__ uint8_t sm8[];
    const int bid = blockIdx.x;
    const int t   = threadIdx.x;

    if (bid < G_CTAS) {
        // ================= GEMM part (frozen R5/R8) =================
        const int lane = t & 31;
        const int warp = t >> 5;
        const int g    = lane >> 2;
        const int tig  = lane & 3;
        const int wm   = warp >> 1;
        const int wn   = warp & 1;
        const int bx   = bid % 12;
        const int by   = bid / 12;
        const int m0   = by * 128;
        const int n0   = bx * 128;

        float acc[2][8][4];
        #pragma unroll
        for (int mt = 0; mt < 2; mt++)
            #pragma unroll
            for (int j = 0; j < 8; j++)
                #pragma unroll
                for (int c = 0; c < 4; c++) acc[mt][j][c] = 0.0f;

        auto load_tile = [&](int buf, int k0) {
            uint8_t* as = sm8 + buf * STAGE8;
            uint8_t* bs = as + TILE8_BYTES;
            #pragma unroll
            for (int i = 0; i < 2; i++) {
                int ch = t + 256 * i;
                int r = ch >> 2;
                int cc = (ch & 3) * 16;
                cp16(smem_u32(as + r * A8_STRIDE + cc),
                     g_Af8 + (size_t)(m0 + r) * HID_ + k0 + cc);
            }
            #pragma unroll
            for (int i = 0; i < 2; i++) {
                int ch = t + 256 * i;
                int r = ch >> 2;
                int cc = (ch & 3) * 16;
                cp16(smem_u32(bs + r * A8_STRIDE + cc),
                     g_WTf8 + (size_t)(n0 + r) * HID_ + k0 + cc);
            }
            CP_COMMIT();
        };

        load_tile(0, 0);
        load_tile(1, 64);
        load_tile(2, 128);

        const int a_row  = lane & 15;
        const int a_coff = (lane >> 4) * 16;
        const int b_row  = (lane & 7) + 8 * (lane >> 4);
        const int b_coff = 16 * ((lane >> 3) & 1);

        for (int kt = 0; kt < 12; kt++) {
            const int buf = kt & 3;
            CP_WAIT2();
            __syncthreads();
            if (kt + 3 < 12) load_tile((kt + 3) & 3, (kt + 3) * 64);
            else             CP_COMMIT();

            const uint8_t* as = sm8 + buf * STAGE8;
            const uint8_t* bs = as + TILE8_BYTES;

            #pragma unroll
            for (int kk = 0; kk < 2; kk++) {
                const int k32 = kk * 32;
                uint32_t af[2][4];
                #pragma unroll
                for (int mt = 0; mt < 2; mt++) {
                    int row = wm * 32 + mt * 16 + a_row;
                    ldsm_x4(af[mt], as + row * A8_STRIDE + k32 + a_coff);
                }
                #pragma unroll
                for (int nt = 0; nt < 4; nt++) {
                    uint32_t bf[4];
                    int row = wn * 64 + nt * 16 + b_row;
                    ldsm_x4(bf, bs + row * A8_STRIDE + k32 + b_coff);
                    mma_fp8(acc[0][2 * nt],     af[0], &bf[0]);
                    mma_fp8(acc[0][2 * nt + 1], af[0], &bf[2]);
                    mma_fp8(acc[1][2 * nt],     af[1], &bf[0]);
                    mma_fp8(acc[1][2 * nt + 1], af[1], &bf[2]);
                }
            }
        }

        // Epilogue: bias + RoPE + e4m3 scatter
        #pragma unroll
        for (int mt = 0; mt < 2; mt++) {
            #pragma unroll
            for (int half = 0; half < 2; half++) {
                const int m  = m0 + wm * 32 + mt * 16 + g + half * 8;
                const int l  = m & (LL_ - 1);
                const int b_ = m >> 9;
                #pragma unroll
                for (int j = 0; j < 8; j++) {
                    const int n = n0 + wn * 64 + j * 8 + 2 * tig;
                    float e = acc[mt][j][half * 2 + 0] + bias[n];
                    float o = acc[mt][j][half * 2 + 1] + bias[n + 1];
                    const int h  = n >> 7;
                    const int qk = (n >> 6) & 1;
                    const int d  = n & 63;
                    const int p  = d >> 1;
                    const float s  = g_sin[l * 32 + p];
                    const float co = g_cos[l * 32 + p];
                    uint16_t v = f2e4m3x2(e * s + o * co, e * co - o * s);
                    uint8_t* dst = (qk ? g_k8 : g_q8)
                        + ((size_t)(b_ * HEADS_ + h) * LL_ + l) * HS_ + d;
                    *(uint16_t*)dst = v;
                }
            }
        }

        // Release: all q/k writes visible, then count up flag[bh]
        __threadfence();
        __syncthreads();
        if (t == 0) {
            const int bh = (by >> 2) * HEADS_ + bx;
            atomicAdd(&g_flag[bh], 1);
        }
        return;
    }

    // ================= ATTN part (2 groups of 128 threads) =================
    const int a   = bid - G_CTAS;     // 0..383
    const int bh  = a >> 2;
    const int pr  = a & 3;
    const int grp = t >> 7;           // 0 or 1
    const int gt  = t & 127;
    const int tm  = pr * 2 + grp;     // 0..7
    const int b_  = bh / HEADS_;
    const int m0  = tm * 64;
    float* obase = out + (size_t)bh * LL_ * LL_;

    uint8_t* Qs  = sm8 + grp * 16384;
    uint8_t* Ks0 = Qs + 5120;
    uint8_t* Ks1 = Qs + 10240;
    int* amrow   = (int*)(sm8 + 32768);     // shared by both groups (same bh)

    // 1) Below-diagonal fills — no dependency, overlaps gemm compute
    {
        const float4 nv = make_float4(NEG_INF_F, NEG_INF_F, NEG_INF_F, NEG_INF_F);
        for (int tn = 0; tn < tm; tn++) {
            float* tb = obase + (size_t)m0 * LL_ + tn * 64;
            #pragma unroll
            for (int i = 0; i < 8; i++) {
                int idx = gt + 128 * i;          // 0..1023
                int r = idx >> 4;
                int c = (idx & 15) * 4;
                stg_cs_f4(&tb[(size_t)r * LL_ + c], nv);
            }
        }
    }
    // 2) attention-mask row (no dependency)
    amrow[t]       = am[b_ * LL_ + t];
    amrow[t + 256] = am[b_ * LL_ + t + 256];

    // 3) Wait for the 4 producer CTAs of this (b,h)
    if (t == 0) {
        while (ld_acq(&g_flag[bh]) < 4) {
            asm volatile("nanosleep.u32 64;");
        }
    }
    __syncthreads();
    __threadfence();

    // 4) Stage Q + first K tile (tn = tm)
    const uint8_t* qb = g_q8 + ((size_t)bh * LL_ + m0) * HS_;
    const uint8_t* kb = g_k8 + ((size_t)bh * LL_ + tm * 64) * HS_;
    #pragma unroll
    for (int i = 0; i < 2; i++) {
        int ch = gt + 128 * i;
        int r = ch >> 2;
        int c = (ch & 3) * 16;
        cp16(smem_u32(Qs + r * QK8_STRIDE + c), qb + r * HS_ + c);
        cp16(smem_u32(Ks0 + r * QK8_STRIDE + c), kb + r * HS_ + c);
    }
    CP_COMMIT();
    CP_WAIT0();
    asm volatile("bar.sync %0, 128;" :: "r"(grp + 1) : "memory");

    const int lane = gt & 31;
    const int warp = gt >> 5;
    const int g    = lane >> 2;
    const int tig  = lane & 3;
    const int wm   = warp >> 1;
    const int wn   = warp & 1;

    const int a_row  = lane & 15;
    const int a_coff = (lane >> 4) * 16;
    const int b_row  = (lane & 7) + 8 * (lane >> 4);
    const int b_coff = 16 * ((lane >> 3) & 1);

    // Hoist Q fragments once
    uint32_t qf[2][4], qf2[2][4];
    #pragma unroll
    for (int mt = 0; mt < 2; mt++) {
        int row = wm * 32 + mt * 16 + a_row;
        ldsm_x4(qf[mt],  Qs + row * QK8_STRIDE + a_coff);
        ldsm_x4(qf2[mt], Qs + row * QK8_STRIDE + 32 + a_coff);
    }

    int buf = 0;
    for (int tn = tm; tn < 8; tn++) {
        uint8_t* Kcur = buf ? Ks1 : Ks0;
        uint8_t* Knxt = buf ? Ks0 : Ks1;
        if (tn + 1 < 8) {
            const uint8_t* kn = g_k8 + ((size_t)bh * LL_ + (tn + 1) * 64) * HS_;
            #pragma unroll
            for (int i = 0; i < 2; i++) {
                int ch = gt + 128 * i;
                int r = ch >> 2;
                int c = (ch & 3) * 16;
                cp16(smem_u32(Knxt + r * QK8_STRIDE + c), kn + r * HS_ + c);
            }
            CP_COMMIT();
        }

        const int n0 = tn * 64;
        float acc[2][4][4];
        #pragma unroll
        for (int mt = 0; mt < 2; mt++)
            #pragma unroll
            for (int j = 0; j < 4; j++)
                #pragma unroll
                for (int c = 0; c < 4; c++) acc[mt][j][c] = 0.0f;

        #pragma unroll
        for (int nt = 0; nt < 2; nt++) {
            uint32_t kf[4];
            int row = wn * 32 + nt * 16 + b_row;
            ldsm_x4(kf, Kcur + row * QK8_STRIDE + b_coff);
            mma_fp8(acc[0][2 * nt],     qf[0], &kf[0]);
            mma_fp8(acc[0][2 * nt + 1], qf[0], &kf[2]);
            mma_fp8(acc[1][2 * nt],     qf[1], &kf[0]);
            mma_fp8(acc[1][2 * nt + 1], qf[1], &kf[2]);
            ldsm_x4(kf, Kcur + row * QK8_STRIDE + 32 + b_coff);
            mma_fp8(acc[0][2 * nt],     qf2[0], &kf[0]);
            mma_fp8(acc[0][2 * nt + 1], qf2[0], &kf[2]);
            mma_fp8(acc[1][2 * nt],     qf2[1], &kf[0]);
            mma_fp8(acc[1][2 * nt + 1], qf2[1], &kf[2]);
        }

        const bool diag = (tn == tm);
        #pragma unroll
        for (int mt = 0; mt < 2; mt++) {
            #pragma unroll
            for (int half = 0; half < 2; half++) {
                const int mi = wm * 32 + mt * 16 + g + half * 8;
                const int m  = m0 + mi;
                const bool rok = (amrow[m] != 0);
                #pragma unroll
                for (int j = 0; j < 4; j++) {
                    const int ni = wn * 32 + j * 8 + 2 * tig;
                    const int n  = n0 + ni;
                    float x0 = acc[mt][j][half * 2 + 0] * 0.125f;
                    float x1 = acc[mt][j][half * 2 + 1] * 0.125f;
                    bool k0 = !rok || amrow[n] == 0;
                    bool k1 = !rok || amrow[n + 1] == 0;
                    if (diag) { k0 |= (m > n); k1 |= (m > n + 1); }
                    if (k0) x0 = NEG_INF_F;
                    if (k1) x1 = NEG_INF_F;
                    stg_cs_f2(&obase[(size_t)m * LL_ + n], x0, x1);
                }
            }
        }

        if (tn + 1 < 8) {
            CP_WAIT0();
            asm volatile("bar.sync %0, 128;" :: "r"(grp + 1) : "memory");
        }
        buf ^= 1;
    }
}

// ---------------------------------------------------------------------------
// Entry point
// ---------------------------------------------------------------------------
extern "C" void kernel_launch(void* const* d_in, const int* in_sizes, int n_in,
                              void* d_out, int out_size) {
    const float* inputs = (const float*)d_in[0];  // [8,512,768]
    const float* W      = (const float*)d_in[1];  // [768,1536]
    const float* bias   = (const float*)d_in[2];  // [1536]
    const int*   amask  = (const int*)d_in[3];    // [8,512]
    float* out = (float*)d_out;                   // [8,12,512,512]

    cudaFuncSetAttribute(fused_gemm_attn,
                         cudaFuncAttributeMaxDynamicSharedMemorySize, G1_DSMEM);

    prep_all<<<NAB_ + NTB_ + NTRB_ + 1, 256>>>(inputs, W);
    fused_gemm_attn<<<G_CTAS + 384, 256, G1_DSMEM>>>(bias, amask, out);
}